// round 15
// baseline (speedup 1.0000x reference)
#include <cuda_runtime.h>
#include <cstdint>

// ---------------- problem constants ----------------
#define D_DIM    64
#define SUBN     256
#define T_LEN    16384
#define N_ROWS   262144
#define ZQ_ELEMS 16777216
#define LOSS_OFF ZQ_ELEMS
#define PERP_OFF (ZQ_ELEMS + 1)
#define IDX_OFF  (ZQ_ELEMS + 2)
#define ROWS_PT  128           // rows per tile (one row per lane PAIR)
#define NTILES   (N_ROWS / ROWS_PT)   // 2048
#define LCAP     8             // per-row candidate list capacity

// ---------------- persistent scratch ----------------
// Invariant: all zero at kernel_launch entry; finalizer re-zeros.
__device__ int          g_counts[SUBN];
__device__ double       g_sse;
__device__ unsigned int g_done;
__device__ unsigned int g_tick;

// ---------------- helpers --------------------------
__device__ __forceinline__ unsigned long long ffma2(unsigned long long a,
                                                    unsigned long long b,
                                                    unsigned long long c) {
    unsigned long long d;
    asm("fma.rn.f32x2 %0, %1, %2, %3;" : "=l"(d) : "l"(a), "l"(b), "l"(c));
    return d;
}
__device__ __forceinline__ float2 unpack2(unsigned long long v) {
    float2 r;
    asm("mov.b64 {%0, %1}, %2;" : "=f"(r.x), "=f"(r.y) : "l"(v));
    return r;
}
__device__ __forceinline__ unsigned long long pack64(float lo, float hi) {
    unsigned long long v;
    asm("mov.b64 %0, {%1, %2};" : "=l"(v) : "f"(lo), "f"(hi));
    return v;
}
__device__ __forceinline__ unsigned long long packdj(float d, int j) {
    return ((unsigned long long)__float_as_uint(d) << 32) | (unsigned)j;
}
__device__ __forceinline__ uint32_t pack4b(int b0, int b1, int b2, int b3) {
    return (uint32_t)(b0 & 255) | ((uint32_t)(b1 & 255) << 8) |
           ((uint32_t)(b2 & 255) << 16) | ((uint32_t)(b3 & 255) << 24);
}

// R1's exact fp32 distance: packed ffma2 dual-chain dot, (zz+ee) - 2*dot.
// z reloaded from global (L1-hot) — identical values => identical bits.
__device__ __forceinline__ float exact_dg(const float4* __restrict__ zrow4,
                                          float zz,
                                          const float* __restrict__ erow,
                                          float eej) {
    unsigned long long a0 = 0ull, a1 = 0ull;
    const float4* e4 = (const float4*)erow;
    #pragma unroll
    for (int i = 0; i < 16; i++) {
        float4 zv = __ldg(zrow4 + i);
        float4 ev = __ldg(e4 + i);
        a0 = ffma2(pack64(zv.x, zv.y), pack64(ev.x, ev.y), a0);
        a1 = ffma2(pack64(zv.z, zv.w), pack64(ev.z, ev.w), a1);
    }
    float2 x0 = unpack2(a0), x1 = unpack2(a1);
    const float dot = (x0.x + x0.y) + (x1.x + x1.y);
    return (zz + eej) - 2.0f * dot;
}

// ==================================================================
__global__ __launch_bounds__(256, 4) void vq_dp4a(const float* __restrict__ z,
                                                  const float* __restrict__ one_hot,
                                                  const float* __restrict__ W,
                                                  float* __restrict__ out,
                                                  int nblocks) {
    __shared__ uint4    Eq[SUBN * 4];             // int8 codebook, 16KB
    __shared__ float    ee[SUBN];
    __shared__ uint32_t slist[ROWS_PT * LCAP];    // per-PAIR candidate lists, 4KB
    __shared__ int      shist[SUBN];
    __shared__ float    sred[8];
    __shared__ float    emax_r[8];
    __shared__ float    sEMAX;
    __shared__ unsigned stile;

    const int tid  = threadIdx.x;
    const int lane = tid & 31;
    const int w    = tid >> 5;
    const int pr   = tid >> 1;      // pair id 0..127
    const int h    = tid & 1;       // half: 0 = dims 0-31, 1 = dims 32-63

    // pos = argmax(one_hot), first-max semantics
    float mv = one_hot[0];
    int pos = 0;
    #pragma unroll
    for (int i = 1; i < 7; i++) {
        float v = one_hot[i];
        if (v > mv) { mv = v; pos = i; }
    }
    const float* Wp = W + (size_t)pos * SUBN * D_DIM;

    // ---- E prep: ee (exact R1 chain) + block max|e| (one E row per thread) ----
    {
        const float4* er4 = (const float4*)(Wp + (size_t)tid * D_DIM);
        float s = 0.f, me = 0.f;
        #pragma unroll
        for (int i = 0; i < 16; i++) {
            float4 e = __ldg(er4 + i);
            s = fmaf(e.x, e.x, s);
            s = fmaf(e.y, e.y, s);
            s = fmaf(e.z, e.z, s);
            s = fmaf(e.w, e.w, s);
            me = fmaxf(me, fmaxf(fmaxf(fabsf(e.x), fabsf(e.y)),
                                 fmaxf(fabsf(e.z), fabsf(e.w))));
        }
        ee[tid] = s;
        #pragma unroll
        for (int o = 16; o > 0; o >>= 1)
            me = fmaxf(me, __shfl_xor_sync(0xffffffffu, me, o));
        if (lane == 0) emax_r[w] = me;
        shist[tid] = 0;
    }
    __syncthreads();
    if (tid == 0) {
        float m = emax_r[0];
        #pragma unroll
        for (int q = 1; q < 8; q++) m = fmaxf(m, emax_r[q]);
        sEMAX = fmaxf(m, 1e-30f);
    }
    __syncthreads();

    const float EMAXE = sEMAX;
    const float SE = 127.0f / EMAXE;
    const float he = 0.5f / SE;

    // quantize E into smem int8 tiles (second pass over E row, L1-hot)
    {
        const float4* er4 = (const float4*)(Wp + (size_t)tid * D_DIM);
        #pragma unroll
        for (int c = 0; c < 4; c++) {
            uint32_t q[4];
            #pragma unroll
            for (int p = 0; p < 4; p++) {
                float4 e = __ldg(er4 + c * 4 + p);
                q[p] = pack4b(__float2int_rn(e.x * SE),
                              __float2int_rn(e.y * SE),
                              __float2int_rn(e.z * SE),
                              __float2int_rn(e.w * SE));
            }
            Eq[tid * 4 + c] = make_uint4(q[0], q[1], q[2], q[3]);
        }
    }
    __syncthreads();

    float sse_loc = 0.f;

    // ---- main loop: global work ticket over 2048 tiles of 128 rows ----
    while (true) {
        __syncthreads();
        if (tid == 0) stile = atomicAdd(&g_tick, 1u);
        __syncthreads();
        const unsigned tile = stile;
        if (tile >= NTILES) break;

        const int n = (int)tile * ROWS_PT + pr;  // this PAIR's row
        const float4* zp = (const float4*)(z + (size_t)n * D_DIM);

        // both lanes: full-row exact zz (R1 chain) + margin terms (identical bits)
        float zz, sumabs, SZ;
        {
            unsigned long long zzacc = 0ull;
            float sa = 0.f, mz = 0.f;
            #pragma unroll
            for (int i = 0; i < 16; i++) {
                float4 v = __ldg(zp + i);
                unsigned long long vx = pack64(v.x, v.y);
                unsigned long long vy = pack64(v.z, v.w);
                zzacc = ffma2(vx, vx, zzacc);
                zzacc = ffma2(vy, vy, zzacc);
                sa += fabsf(v.x) + fabsf(v.y) + fabsf(v.z) + fabsf(v.w);
                mz = fmaxf(mz, fmaxf(fmaxf(fabsf(v.x), fabsf(v.y)),
                                     fmaxf(fabsf(v.z), fabsf(v.w))));
            }
            float2 p = unpack2(zzacc);
            zz = p.x + p.y;
            sumabs = sa;
            SZ = 127.0f / fmaxf(mz, 1e-30f);
        }

        // quantize OWN half (8 u32 = 32 dims), L1-hot reload
        uint32_t qz[8];
        #pragma unroll
        for (int i = 0; i < 8; i++) {
            float4 v = __ldg(zp + h * 8 + i);
            qz[i] = pack4b(__float2int_rn(v.x * SZ),
                           __float2int_rn(v.y * SZ),
                           __float2int_rn(v.z * SZ),
                           __float2int_rn(v.w * SZ));
        }

        const float hz    = 0.5f / SZ;
        const float negc2 = -2.0f / (SZ * SE);
        // rigorous rescue margin: 4*eps_dot + slop
        const float marg  = 4.0f * (he * sumabs + 64.0f * hz * (EMAXE + he))
                            + 1e-6f;

        // seed running best with 8 strided probes
        float best = 3.402823466e38f;
        #pragma unroll
        for (int t = 0; t < 8; t++) {
            const int j = t * 32 + 16;
            uint4 e0 = Eq[j * 4 + h * 2];
            uint4 e1 = Eq[j * 4 + h * 2 + 1];
            int a0 = 0, a1 = 0, a2 = 0, a3 = 0;
            a0 = __dp4a((int)e0.x, (int)qz[0], a0);
            a1 = __dp4a((int)e0.y, (int)qz[1], a1);
            a2 = __dp4a((int)e0.z, (int)qz[2], a2);
            a3 = __dp4a((int)e0.w, (int)qz[3], a3);
            a0 = __dp4a((int)e1.x, (int)qz[4], a0);
            a1 = __dp4a((int)e1.y, (int)qz[5], a1);
            a2 = __dp4a((int)e1.z, (int)qz[6], a2);
            a3 = __dp4a((int)e1.w, (int)qz[7], a3);
            int own = (a0 + a1) + (a2 + a3);
            int tot = own + __shfl_xor_sync(0xffffffffu, own, 1);
            best = fminf(best, fmaf((float)tot, negc2, ee[j]));
        }

        // filter scan: half-row dp4a + pair combine (scores identical both lanes)
        int cnt = 0;
        for (int j = 0; j < SUBN; j++) {
            uint4 e0 = Eq[j * 4 + h * 2];
            uint4 e1 = Eq[j * 4 + h * 2 + 1];
            int a0 = 0, a1 = 0, a2 = 0, a3 = 0;
            a0 = __dp4a((int)e0.x, (int)qz[0], a0);
            a1 = __dp4a((int)e0.y, (int)qz[1], a1);
            a2 = __dp4a((int)e0.z, (int)qz[2], a2);
            a3 = __dp4a((int)e0.w, (int)qz[3], a3);
            a0 = __dp4a((int)e1.x, (int)qz[4], a0);
            a1 = __dp4a((int)e1.y, (int)qz[5], a1);
            a2 = __dp4a((int)e1.z, (int)qz[6], a2);
            a3 = __dp4a((int)e1.w, (int)qz[7], a3);
            int own = (a0 + a1) + (a2 + a3);
            int tot = own + __shfl_xor_sync(0xffffffffu, own, 1);
            const float s = fmaf((float)tot, negc2, ee[j]);
            if (s <= best + marg) {
                if (cnt < LCAP && h == 0) slist[pr * LCAP + cnt] = (uint32_t)j;
                cnt++;
            }
            best = fminf(best, s);
        }
        __syncwarp();   // odd lanes read slist written by even lanes

        // resolve with the exact R1 chain; candidates split by lane parity
        unsigned long long rb = ~0ull;
        if (cnt > LCAP) {
            for (int j = h; j < SUBN; j += 2) {
                float de = exact_dg(zp, zz, Wp + (size_t)j * D_DIM, ee[j]);
                unsigned long long p = packdj(de, j);
                if (p < rb) rb = p;
            }
        } else {
            for (int i = h; i < cnt; i += 2) {
                int j = (int)slist[pr * LCAP + i];
                float de = exact_dg(zp, zz, Wp + (size_t)j * D_DIM, ee[j]);
                unsigned long long p = packdj(de, j);
                if (p < rb) rb = p;
            }
        }
        {
            unsigned long long o = __shfl_xor_sync(0xffffffffu, rb, 1);
            if (o < rb) rb = o;
        }
        const int   jwin = (int)(rb & 0xffffffffu);
        const float dwin = __uint_as_float((uint32_t)(rb >> 32));

        if (h == 0) {
            atomicAdd(&shist[jwin], 1);
            sse_loc += dwin;                    // exact ||z - e||^2 (R1 chain)
            out[IDX_OFF + n] = (float)jwin;
        }

        // z_q transposed write: each lane writes its 32 d-planes
        {
            const float4* er4 = (const float4*)(Wp + (size_t)jwin * D_DIM);
            const int b = n >> 14, t = n & (T_LEN - 1);
            float* ob = out + (size_t)b * D_DIM * T_LEN + t;
            #pragma unroll
            for (int i = 0; i < 8; i++) {
                float4 e = __ldg(er4 + h * 8 + i);
                const int d0 = h * 32 + 4 * i;
                ob[(size_t)(d0 + 0) * T_LEN] = e.x;
                ob[(size_t)(d0 + 1) * T_LEN] = e.y;
                ob[(size_t)(d0 + 2) * T_LEN] = e.z;
                ob[(size_t)(d0 + 3) * T_LEN] = e.w;
            }
        }
    }

    // ---- block reductions + global flush ----
    __syncthreads();
    float s = sse_loc;
    #pragma unroll
    for (int o = 16; o > 0; o >>= 1)
        s += __shfl_down_sync(0xffffffffu, s, o);
    if (lane == 0) sred[w] = s;
    __syncthreads();
    if (tid == 0) {
        float tot = 0.f;
        #pragma unroll
        for (int q = 0; q < 8; q++) tot += sred[q];
        atomicAdd(&g_sse, (double)tot);
    }
    atomicAdd(&g_counts[tid], shist[tid]);

    // ---- last-block finalize ----
    __threadfence();
    __syncthreads();
    if (tid == 0) stile = atomicAdd(&g_done, 1u);
    __syncthreads();
    if (stile == (unsigned)(nblocks - 1)) {
        float c = (float)g_counts[tid];
        g_counts[tid] = 0;                      // restore zero-invariant
        float em = c * (1.0f / 262144.0f);
        float v = em * logf(em + 1e-10f);
        #pragma unroll
        for (int o = 16; o > 0; o >>= 1)
            v += __shfl_down_sync(0xffffffffu, v, o);
        if (lane == 0) sred[w] = v;
        __syncthreads();
        if (tid == 0) {
            float H = 0.f;
            #pragma unroll
            for (int q = 0; q < 8; q++) H += sred[q];
            out[PERP_OFF] = expf(-H);
            double sse = g_sse;
            g_sse = 0.0;
            float m = (float)(sse * (1.0 / 16777216.0));
            out[LOSS_OFF] = 0.25f * m + m;      // BETA*mse + mse
            g_tick = 0;                          // restore for next replay
            g_done = 0;
        }
    }
}

// ------------------------------------------------------------------
extern "C" void kernel_launch(void* const* d_in, const int* in_sizes, int n_in,
                              void* d_out, int out_size) {
    const float* z       = (const float*)d_in[0];
    const float* one_hot = (const float*)d_in[1];
    const float* W       = (const float*)d_in[2];
    float* out           = (float*)d_out;

    int nsm = 148;
    cudaDeviceGetAttribute(&nsm, cudaDevAttrMultiProcessorCount, 0);
    if (nsm <= 0) nsm = 148;
    const int nblocks = nsm * 4;

    vq_dp4a<<<nblocks, 256>>>(z, one_hot, W, out, nblocks);
}

// round 16
// speedup vs baseline: 10.1541x; 10.1541x over previous
#include <cuda_runtime.h>
#include <cstdint>

// ---------------- problem constants ----------------
#define D_DIM    64
#define SUBN     256
#define T_LEN    16384
#define N_ROWS   262144
#define ZQ_ELEMS 16777216
#define LOSS_OFF ZQ_ELEMS
#define PERP_OFF (ZQ_ELEMS + 1)
#define IDX_OFF  (ZQ_ELEMS + 2)
#define NTILES   1024          // 256 rows per tile
#define ESTR     68            // padded smem row stride (floats)

// ---------------- persistent scratch ----------------
// Invariant: all zero at kernel_launch entry; finalizer re-zeros.
__device__ int          g_counts[SUBN];
__device__ double       g_sse;
__device__ unsigned int g_done;

// ---------------- helpers --------------------------
__device__ __forceinline__ unsigned long long ffma2(unsigned long long a,
                                                    unsigned long long b,
                                                    unsigned long long c) {
    unsigned long long d;
    asm("fma.rn.f32x2 %0, %1, %2, %3;" : "=l"(d) : "l"(a), "l"(b), "l"(c));
    return d;
}
__device__ __forceinline__ float2 unpack2(unsigned long long v) {
    float2 r;
    asm("mov.b64 {%0, %1}, %2;" : "=f"(r.x), "=f"(r.y) : "l"(v));
    return r;
}

// ==================================================================
// One persistent kernel. Block layout identical to R1's vq_main:
// one thread per z row, 256 rows per tile, codebook resident in smem.
// ==================================================================
__global__ __launch_bounds__(256, 2) void vq_main(const float* __restrict__ z,
                                                  const float* __restrict__ one_hot,
                                                  const float* __restrict__ W,
                                                  float* __restrict__ out,
                                                  int nblocks) {
    extern __shared__ float E_sp[];            // [256][ESTR] padded codebook
    __shared__ float    sEE[SUBN];
    __shared__ int      shist[SUBN];
    __shared__ float    sred[8];
    __shared__ unsigned sdone;

    const int tid = threadIdx.x;

    // pos = argmax(one_hot), first-max semantics (R1 chain)
    float mv = one_hot[0];
    int pos = 0;
    #pragma unroll
    for (int i = 1; i < 7; i++) {
        float v = one_hot[i];
        if (v > mv) { mv = v; pos = i; }
    }
    const float* Wp = W + (size_t)pos * SUBN * D_DIM;

    // Load selected codebook into padded smem (coalesced float4) — R1 verbatim
    {
        const float4* Wsrc = (const float4*)Wp;
        #pragma unroll 4
        for (int i = tid; i < SUBN * D_DIM / 4; i += 256) {
            int row = i >> 4;        // 16 float4 per 64-float row
            int k4  = i & 15;
            *(float4*)&E_sp[row * ESTR + k4 * 4] = Wsrc[i];
        }
    }
    // ee[j] via R1's exact sequential fmaf chain (from global row)
    {
        const float* Er = Wp + (size_t)tid * D_DIM;
        float s = 0.f;
        #pragma unroll
        for (int k = 0; k < D_DIM; k++) {
            float v = Er[k];
            s = fmaf(v, v, s);
        }
        sEE[tid]   = s;
        shist[tid] = 0;
    }
    __syncthreads();

    float sse_loc = 0.f;

    // ---- grid-stride over tiles; NO per-tile barrier (E_sp is read-only) ----
    for (int tile = blockIdx.x; tile < NTILES; tile += nblocks) {
        const int n = tile * 256 + tid;          // this thread's row
        const ulonglong2* zp = (const ulonglong2*)(z + (size_t)n * D_DIM);

        // z row as 32 packed f32x2; ||z||^2 — R1 verbatim
        unsigned long long z2[32];
        unsigned long long zzacc = 0ull;
        #pragma unroll
        for (int i = 0; i < 16; i++) {
            ulonglong2 v = zp[i];
            z2[2 * i]     = v.x;
            z2[2 * i + 1] = v.y;
            zzacc = ffma2(v.x, v.x, zzacc);
            zzacc = ffma2(v.y, v.y, zzacc);
        }
        float2 zzp = unpack2(zzacc);
        const float zz = zzp.x + zzp.y;

        // Argmin over 256 codes — R1 verbatim (d = (zz+ee[j]) - 2*dot)
        float best = 3.402823466e38f;
        int   bj   = 0;
        #pragma unroll 2
        for (int j = 0; j < SUBN; j++) {
            const ulonglong2* ej = (const ulonglong2*)&E_sp[j * ESTR];
            unsigned long long acc0 = 0ull, acc1 = 0ull;
            #pragma unroll
            for (int i = 0; i < 16; i++) {
                ulonglong2 e = ej[i];
                acc0 = ffma2(z2[2 * i],     e.x, acc0);
                acc1 = ffma2(z2[2 * i + 1], e.y, acc1);
            }
            float2 a0 = unpack2(acc0);
            float2 a1 = unpack2(acc1);
            float dot = (a0.x + a0.y) + (a1.x + a1.y);
            float t1 = zz + sEE[j];
            float dc = t1 - 2.0f * dot;
            if (dc < best) { best = dc; bj = j; }   // strict < => first index
        }

        atomicAdd(&shist[bj], 1);
        sse_loc += best;                        // best == ||z - e_bj||^2

        out[IDX_OFF + n] = (float)bj;

        // z_q transposed write (coalesced along t) — R1 verbatim
        const int b = n >> 14;                  // /16384
        const int t = n & (T_LEN - 1);
        float* ob = out + (size_t)b * D_DIM * T_LEN + t;
        const float* er = &E_sp[bj * ESTR];
        #pragma unroll
        for (int d0 = 0; d0 < D_DIM; d0 += 4) {
            float4 v = *(const float4*)&er[d0];
            ob[(size_t)(d0 + 0) * T_LEN] = v.x;
            ob[(size_t)(d0 + 1) * T_LEN] = v.y;
            ob[(size_t)(d0 + 2) * T_LEN] = v.z;
            ob[(size_t)(d0 + 3) * T_LEN] = v.w;
        }
    }

    // ---- block reductions + global flush ----
    __syncthreads();                            // shist stable
    float s = sse_loc;
    #pragma unroll
    for (int o = 16; o > 0; o >>= 1)
        s += __shfl_down_sync(0xffffffffu, s, o);
    if ((tid & 31) == 0) sred[tid >> 5] = s;
    __syncthreads();
    if (tid == 0) {
        float tot = 0.f;
        #pragma unroll
        for (int q = 0; q < 8; q++) tot += sred[q];
        atomicAdd(&g_sse, (double)tot);
    }
    atomicAdd(&g_counts[tid], shist[tid]);

    // ---- last-block finalize ----
    __threadfence();
    __syncthreads();
    if (tid == 0) sdone = atomicAdd(&g_done, 1u);
    __syncthreads();
    if (sdone == (unsigned)(nblocks - 1)) {
        float c = (float)g_counts[tid];
        g_counts[tid] = 0;                      // restore zero-invariant
        float em = c * (1.0f / 262144.0f);
        float v = em * logf(em + 1e-10f);
        #pragma unroll
        for (int o = 16; o > 0; o >>= 1)
            v += __shfl_down_sync(0xffffffffu, v, o);
        if ((tid & 31) == 0) sred[tid >> 5] = v;
        __syncthreads();
        if (tid == 0) {
            float H = 0.f;
            #pragma unroll
            for (int q = 0; q < 8; q++) H += sred[q];
            out[PERP_OFF] = expf(-H);
            double sse = g_sse;
            g_sse = 0.0;                        // restore zero-invariant
            float m = (float)(sse * (1.0 / 16777216.0));
            out[LOSS_OFF] = 0.25f * m + m;      // BETA*mse + mse
            g_done = 0;
        }
    }
}

// ------------------------------------------------------------------
extern "C" void kernel_launch(void* const* d_in, const int* in_sizes, int n_in,
                              void* d_out, int out_size) {
    const float* z       = (const float*)d_in[0];
    const float* one_hot = (const float*)d_in[1];
    const float* W       = (const float*)d_in[2];
    float* out           = (float*)d_out;

    int nsm = 148;
    cudaDeviceGetAttribute(&nsm, cudaDevAttrMultiProcessorCount, 0);
    if (nsm <= 0) nsm = 148;
    const int nblocks = nsm * 2;

    const int smem_bytes = SUBN * ESTR * 4;     // 69632B dynamic (E_sp)
    cudaFuncSetAttribute(vq_main, cudaFuncAttributeMaxDynamicSharedMemorySize,
                         smem_bytes);

    vq_main<<<nblocks, 256, smem_bytes>>>(z, one_hot, W, out, nblocks);
}